// round 15
// baseline (speedup 1.0000x reference)
#include <cuda_runtime.h>
#include <cuda_fp16.h>
#include <cstdint>

#define SLEN    2048
#define DMODEL  1024
#define NHEAD   16
#define DKH     64
#define NB      4
#define MTOT    (NB * SLEN)     // 8192

// ---------------- scratch (allocation-free: __device__ globals) ----------------
// pre-split fp16 hi/lo Q/K (V hi-only), layout [B,H,S,64].
// Q is pre-scaled by 0.125*log2(e); Q and K are d-PAIR-PERMUTED; V is natural.
__device__ __half g_Qh[(size_t)NB * NHEAD * SLEN * DKH];
__device__ __half g_Ql[(size_t)NB * NHEAD * SLEN * DKH];
__device__ __half g_Kh[(size_t)NB * NHEAD * SLEN * DKH];
__device__ __half g_Kl[(size_t)NB * NHEAD * SLEN * DKH];
__device__ __half g_Vh[(size_t)NB * NHEAD * SLEN * DKH];

// fp16 hi/lo split GEMM operands, pair-permuted per 16-k group on u32 pairs:
// u32 slot order per 8-u32 group = [pr0,pr4,pr1,pr5,pr2,pr6,pr3,pr7]
__device__ __half g_Xh[(size_t)3 * MTOT * DMODEL];   // q,k,v inputs
__device__ __half g_Xl[(size_t)3 * MTOT * DMODEL];
__device__ __half g_Wh[(size_t)4 * DMODEL * DMODEL]; // wq,wk,wv,wo
__device__ __half g_Wl[(size_t)4 * DMODEL * DMODEL];
__device__ __half g_AOh[(size_t)MTOT * DMODEL];      // attn out
__device__ __half g_AOl[(size_t)MTOT * DMODEL];

// ---------------- helpers ------------------------------------------------------
__device__ __forceinline__ uint32_t smem_u32(const void* p) {
    uint32_t a;
    asm("{ .reg .u64 t; cvta.to.shared.u64 t, %1; cvt.u32.u64 %0, t; }" : "=r"(a) : "l"(p));
    return a;
}

__device__ __forceinline__ void cp16(uint32_t dst, const void* src) {
    asm volatile("cp.async.cg.shared.global [%0], [%1], 16;" :: "r"(dst), "l"(src));
}
#define CP_COMMIT() asm volatile("cp.async.commit_group;")
#define CP_WAIT(n)  asm volatile("cp.async.wait_group %0;" :: "n"(n))

__device__ __forceinline__ uint2 ldsm_x2_trans(uint32_t addr) {
    uint2 r;
    asm volatile("ldmatrix.sync.aligned.m8n8.x2.trans.shared.b16 {%0,%1}, [%2];"
                 : "=r"(r.x), "=r"(r.y) : "r"(addr));
    return r;
}

__device__ __forceinline__ uint32_t h2u(half2 h) {
    return *reinterpret_cast<uint32_t*>(&h);
}

__device__ __forceinline__ void mma_f16(float c[4], const uint32_t a[4],
                                        uint32_t b0, uint32_t b1) {
    asm volatile(
        "mma.sync.aligned.m16n8k16.row.col.f32.f16.f16.f32 "
        "{%0,%1,%2,%3}, {%4,%5,%6,%7}, {%8,%9}, {%0,%1,%2,%3};"
        : "+f"(c[0]), "+f"(c[1]), "+f"(c[2]), "+f"(c[3])
        : "r"(a[0]), "r"(a[1]), "r"(a[2]), "r"(a[3]), "r"(b0), "r"(b1));
}

// ---------------- fused fp16-split pre-convert (all 7 tensors) -----------------
// Each thread handles one 16-float group: writes 8 hi u32 + 8 lo u32, permuted.
__global__ __launch_bounds__(256) void conv_all_kernel(
    const float* __restrict__ q, const float* __restrict__ k, const float* __restrict__ v,
    const float* __restrict__ wq, const float* __restrict__ wk,
    const float* __restrict__ wv, const float* __restrict__ wo)
{
    int b = blockIdx.x;
    const float* src;
    __half* dh;
    __half* dl;
    size_t i;
    if (b < 6144) {
        int sel = b >> 11;
        src = (sel == 0) ? q : (sel == 1) ? k : v;
        dh = g_Xh + (size_t)sel * MTOT * DMODEL;
        dl = g_Xl + (size_t)sel * MTOT * DMODEL;
        i = (size_t)(b & 2047) * 256 + threadIdx.x;
    } else {
        int sel = (b - 6144) >> 8;
        src = (sel == 0) ? wq : (sel == 1) ? wk : (sel == 2) ? wv : wo;
        dh = g_Wh + (size_t)sel * DMODEL * DMODEL;
        dl = g_Wl + (size_t)sel * DMODEL * DMODEL;
        i = (size_t)((b - 6144) & 255) * 256 + threadIdx.x;
    }
    const float4* s4 = (const float4*)src + 4 * i;
    float4 v0 = s4[0], v1 = s4[1], v2 = s4[2], v3 = s4[3];
    float px[16] = { v0.x, v0.y, v0.z, v0.w, v1.x, v1.y, v1.z, v1.w,
                     v2.x, v2.y, v2.z, v2.w, v3.x, v3.y, v3.z, v3.w };
    uint32_t hu[8], lu[8];
#pragma unroll
    for (int j = 0; j < 8; j++) {
        half2 h = __floats2half2_rn(px[2 * j], px[2 * j + 1]);
        half2 l = __floats2half2_rn(px[2 * j] - __low2float(h),
                                    px[2 * j + 1] - __high2float(h));
        hu[j] = h2u(h);
        lu[j] = h2u(l);
    }
    uint4* oh = (uint4*)dh + 2 * i;
    uint4* ol = (uint4*)dl + 2 * i;
    oh[0] = make_uint4(hu[0], hu[4], hu[1], hu[5]);
    oh[1] = make_uint4(hu[2], hu[6], hu[3], hu[7]);
    ol[0] = make_uint4(lu[0], lu[4], lu[1], lu[5]);
    ol[1] = make_uint4(lu[2], lu[6], lu[3], lu[7]);
}

// ======================= split-fp16 tensor-core GEMM ===========================
// 128x128 CTA tile, 256 threads (2m x 4n warps, warp tile 64x32), BK=32, 2-stage.
// smem arrays per stage: Ahi, Alo, Bhi, Blo each [128][24] u32 (16 used).
#define BK2 32
#define P24 24
#define HS_U (128 * P24)                      // 3072 u32 per array
#define STG_U (4 * HS_U)                      // 12288 u32 per stage
#define GEMM_SMEM (2 * STG_U * 4)             // 98304 bytes

__device__ __forceinline__ void gemm_f16_main(
    const uint32_t* __restrict__ Xh, const uint32_t* __restrict__ Xl,
    const uint32_t* __restrict__ Wh, const uint32_t* __restrict__ Wl,
    int m0, int n0, float acc[4][4][4])
{
    extern __shared__ uint32_t su[];
    const int tid  = threadIdx.x;
    const int lane = tid & 31, warp = tid >> 5;
    const int wm = warp >> 2, wn = warp & 3;
    const int g  = lane >> 2, tg = lane & 3;
    const uint32_t sb = smem_u32(su);

    // per thread 8 cp16 per stage: 4 arrays x 128 rows x 4 chunks = 2048
#define ISSUE_TILE(kt, s)                                                           \
    do {                                                                            \
        _Pragma("unroll")                                                           \
        for (int _j = 0; _j < 8; _j++) {                                            \
            int _seg = tid + _j * 256;                                              \
            int _arr = _seg >> 9;                                                   \
            int _w   = _seg & 511;                                                  \
            int _row = _w >> 2;                                                     \
            int _ch  = _w & 3;                                                      \
            const uint32_t* _p = (_arr == 0) ? Xh : (_arr == 1) ? Xl                \
                               : (_arr == 2) ? Wh : Wl;                             \
            int _rb = (_arr < 2) ? m0 : n0;                                         \
            cp16(sb + (uint32_t)((s) * STG_U + _arr * HS_U + _row * P24 + _ch * 4) * 4, \
                 _p + (size_t)(_rb + _row) * 512 + (kt) * 16 + _ch * 4);            \
        }                                                                           \
    } while (0)

    const int NT = DMODEL / BK2;              // 32
    ISSUE_TILE(0, 0); CP_COMMIT();
    ISSUE_TILE(1, 1); CP_COMMIT();

    for (int kt = 0; kt < NT; kt++) {
        CP_WAIT(1);
        __syncthreads();

        const int s = kt & 1;
        const uint32_t* Ah = su + s * STG_U;
        const uint32_t* Al = Ah + HS_U;
        const uint32_t* Bh = Ah + 2 * HS_U;
        const uint32_t* Bl = Ah + 3 * HS_U;

#pragma unroll
        for (int s16 = 0; s16 < 2; s16++) {
            const int colb = s16 * 8 + 2 * tg;
            uint32_t bh[4][2], bl[4][2];
#pragma unroll
            for (int fn = 0; fn < 4; fn++) {
                const int r = (wn * 32 + fn * 8 + g) * P24 + colb;
                uint2 th = *(const uint2*)(Bh + r);
                uint2 tl = *(const uint2*)(Bl + r);
                bh[fn][0] = th.x; bh[fn][1] = th.y;
                bl[fn][0] = tl.x; bl[fn][1] = tl.y;
            }
#pragma unroll
            for (int fm = 0; fm < 4; fm++) {
                const int rr  = (wm * 64 + fm * 16 + g) * P24 + colb;
                uint2 h0 = *(const uint2*)(Ah + rr);
                uint2 h1 = *(const uint2*)(Ah + rr + 8 * P24);
                uint32_t ahi[4] = { h0.x, h1.x, h0.y, h1.y };
                uint2 l0 = *(const uint2*)(Al + rr);
                uint2 l1 = *(const uint2*)(Al + rr + 8 * P24);
                uint32_t alo[4] = { l0.x, l1.x, l0.y, l1.y };
#pragma unroll
                for (int fn = 0; fn < 4; fn++) {
                    mma_f16(acc[fm][fn], ahi, bh[fn][0], bh[fn][1]);
                    mma_f16(acc[fm][fn], ahi, bl[fn][0], bl[fn][1]);
                    mma_f16(acc[fm][fn], alo, bh[fn][0], bh[fn][1]);
                }
            }
        }

        __syncthreads();
        if (kt + 2 < NT) ISSUE_TILE(kt + 2, s);
        CP_COMMIT();
    }
#undef ISSUE_TILE
}

// ---------------- QKV projection -> pre-split fp16 hi/lo (V hi-only) -----------
#define QSCALE 0.180336880f

__global__ __launch_bounds__(256, 2) void qkv_f16_kernel(
    const float* __restrict__ bq, const float* __restrict__ bk, const float* __restrict__ bv)
{
    const int z = blockIdx.z;
    const uint32_t* Xh = (const uint32_t*)g_Xh + (size_t)z * MTOT * DMODEL / 2;
    const uint32_t* Xl = (const uint32_t*)g_Xl + (size_t)z * MTOT * DMODEL / 2;
    const uint32_t* Wh = (const uint32_t*)g_Wh + (size_t)z * DMODEL * DMODEL / 2;
    const uint32_t* Wl = (const uint32_t*)g_Wl + (size_t)z * DMODEL * DMODEL / 2;
    const float* Bb   = (z == 0) ? bq : (z == 1) ? bk : bv;
    __half* Hh        = (z == 0) ? g_Qh : (z == 1) ? g_Kh : g_Vh;
    __half* Hl        = (z == 0) ? g_Ql : g_Kl;   // unused for z==2
    const float scale = (z == 0) ? QSCALE : 1.0f;

    const int m0 = blockIdx.y * 128, n0 = blockIdx.x * 128;
    float acc[4][4][4];
#pragma unroll
    for (int i = 0; i < 4; i++)
#pragma unroll
        for (int j = 0; j < 4; j++)
#pragma unroll
            for (int t = 0; t < 4; t++) acc[i][j][t] = 0.f;

    gemm_f16_main(Xh, Xl, Wh, Wl, m0, n0, acc);

    const int tid  = threadIdx.x;
    const int lane = tid & 31, warp = tid >> 5;
    const int wm = warp >> 2, wn = warp & 3;
    const int g  = lane >> 2, tg = lane & 3;

#pragma unroll
    for (int fn = 0; fn < 4; fn++) {
        const int n  = n0 + wn * 32 + fn * 8 + 2 * tg;
        const int hh = n >> 6, dd = n & 63;
        int ddw;
        if (z < 2) {
            int kk  = dd >> 1;
            int grp = kk >> 3, pig = kk & 7;
            int pp  = ((pig & 3) << 1) | (pig >> 2);
            ddw = (grp * 8 + pp) * 2;
        } else {
            ddw = dd;
        }
        const float b0 = Bb[n], b1 = Bb[n + 1];
#pragma unroll
        for (int fm = 0; fm < 4; fm++) {
#pragma unroll
            for (int half_ = 0; half_ < 2; half_++) {
                const int m  = m0 + wm * 64 + fm * 16 + g + half_ * 8;
                const int bb = m >> 11;
                const int ss = m & (SLEN - 1);
                float v0 = (acc[fm][fn][half_ * 2 + 0] + b0) * scale;
                float v1 = (acc[fm][fn][half_ * 2 + 1] + b1) * scale;
                half2 hi = __floats2half2_rn(v0, v1);
                size_t idx = (((size_t)bb * NHEAD + hh) * SLEN + ss) * DKH + ddw;
                *(half2*)(Hh + idx) = hi;
                if (z < 2) {
                    half2 lo = __floats2half2_rn(v0 - __low2float(hi), v1 - __high2float(hi));
                    *(half2*)(Hl + idx) = lo;
                }
            }
        }
    }
}

// ---------------- output projection -------------------------------------------
__global__ __launch_bounds__(256, 2) void outproj_f16_kernel(
    const float* __restrict__ Bb, float* __restrict__ Out)
{
    const uint32_t* Wh = (const uint32_t*)g_Wh + (size_t)3 * DMODEL * DMODEL / 2;
    const uint32_t* Wl = (const uint32_t*)g_Wl + (size_t)3 * DMODEL * DMODEL / 2;
    const int m0 = blockIdx.y * 128, n0 = blockIdx.x * 128;
    float acc[4][4][4];
#pragma unroll
    for (int i = 0; i < 4; i++)
#pragma unroll
        for (int j = 0; j < 4; j++)
#pragma unroll
            for (int t = 0; t < 4; t++) acc[i][j][t] = 0.f;

    gemm_f16_main((const uint32_t*)g_AOh, (const uint32_t*)g_AOl, Wh, Wl, m0, n0, acc);

    const int tid  = threadIdx.x;
    const int lane = tid & 31, warp = tid >> 5;
    const int wm = warp >> 2, wn = warp & 3;
    const int g  = lane >> 2, tg = lane & 3;

#pragma unroll
    for (int fn = 0; fn < 4; fn++) {
        const int n = n0 + wn * 32 + fn * 8 + 2 * tg;
        const float b0 = Bb[n], b1 = Bb[n + 1];
#pragma unroll
        for (int fm = 0; fm < 4; fm++) {
#pragma unroll
            for (int half_ = 0; half_ < 2; half_++) {
                const int m = m0 + wm * 64 + fm * 16 + g + half_ * 8;
                *(float2*)(Out + (size_t)m * DMODEL + n) =
                    make_float2(acc[fm][fn][half_ * 2 + 0] + b0,
                                acc[fm][fn][half_ * 2 + 1] + b1);
            }
        }
    }
}

// ============ Flash attention: 128-row tiles, 2-stage, P hi-only, V hi-only ====
// smem per stage (u32): K hi [64][40], K lo [64][40], V hi [64][36]
#define KPITCH 40
#define VPITCH 36
#define ST_KHI 0
#define ST_KLO 2560
#define ST_VHI 5120
#define STAGE_U 7424
#define ATTN_SMEM_BYTES (2 * STAGE_U * 4)     // 59392

__global__ __launch_bounds__(256, 2) void attn_hmma_kernel() {
    extern __shared__ uint32_t smu[];

    const int qb = 15 - blockIdx.x;            // long CTAs first
    const int bh = blockIdx.y;
    const size_t base = (size_t)bh * SLEN * DKH;
    const __half* Khg = g_Kh + base;
    const __half* Klg = g_Kl + base;
    const __half* Vhg = g_Vh + base;

    const int tid  = threadIdx.x;
    const int lane = tid & 31, warp = tid >> 5;
    const int g  = lane >> 2, tg = lane & 3;
    const int row0 = warp * 16;
    const uint32_t sb = smem_u32(smu);

#define ATTN_ISSUE(kb_, s_)                                                         \
    do {                                                                            \
        _Pragma("unroll")                                                           \
        for (int _j = 0; _j < 4; _j++) {                                            \
            int _t = tid + _j * 256;          /* 0..1023: K hi/lo */                \
            int _row = _t >> 4;                                                     \
            int _ch = _t & 15;                                                      \
            int _c7 = _ch & 7;                                                      \
            const __half* _ks = ((_ch < 8) ? Khg : Klg)                             \
                                + (size_t)((kb_) * 64 + _row) * DKH + _c7 * 8;      \
            cp16(sb + (uint32_t)((s_) * STAGE_U + ((_ch < 8) ? ST_KHI : ST_KLO)     \
                                  + _row * KPITCH + _c7 * 4) * 4, _ks);             \
        }                                                                           \
        _Pragma("unroll")                                                           \
        for (int _j = 0; _j < 2; _j++) {                                            \
            int _t = tid + _j * 256;          /* 0..511: V hi */                    \
            int _row = _t >> 3;                                                     \
            int _c7 = _t & 7;                                                       \
            const __half* _vs = Vhg + (size_t)((kb_) * 64 + _row) * DKH + _c7 * 8;  \
            cp16(sb + (uint32_t)((s_) * STAGE_U + ST_VHI                            \
                                  + _row * VPITCH + _c7 * 4) * 4, _vs);             \
        }                                                                           \
    } while (0)

    ATTN_ISSUE(0, 0); CP_COMMIT();
    ATTN_ISSUE(1, 1); CP_COMMIT();

    // ---- Q fragments -> registers (pair-permuted global, LDG.64) ----
    uint32_t qh[4][4], ql[4][4];
    {
        const uint32_t* Qg  = (const uint32_t*)g_Qh + (base >> 1)
                              + (size_t)(qb * 128 + row0 + g) * 32;
        const uint32_t* Qgl = (const uint32_t*)g_Ql + (base >> 1)
                              + (size_t)(qb * 128 + row0 + g) * 32;
#pragma unroll
        for (int ks = 0; ks < 4; ks++) {
            uint2 a0 = *(const uint2*)(Qg + ks * 8 + 2 * tg);
            uint2 a1 = *(const uint2*)(Qg + 8 * 32 + ks * 8 + 2 * tg);
            qh[ks][0] = a0.x; qh[ks][1] = a1.x; qh[ks][2] = a0.y; qh[ks][3] = a1.y;
            uint2 b0 = *(const uint2*)(Qgl + ks * 8 + 2 * tg);
            uint2 b1 = *(const uint2*)(Qgl + 8 * 32 + ks * 8 + 2 * tg);
            ql[ks][0] = b0.x; ql[ks][1] = b1.x; ql[ks][2] = b0.y; ql[ks][3] = b1.y;
        }
    }

    float acc_o[8][4];
#pragma unroll
    for (int j = 0; j < 8; j++)
#pragma unroll
        for (int t = 0; t < 4; t++) acc_o[j][t] = 0.f;
    float m_run[2] = {-1.0e30f, -1.0e30f};
    float l_run[2] = {0.f, 0.f};

    const int ntiles = 2 * (qb + 1);
    for (int kb = 0; kb < ntiles; kb++) {
        CP_WAIT(1);
        __syncthreads();

        const int s = kb & 1;
        const uint32_t* Khi_s = smu + s * STAGE_U + ST_KHI;
        const uint32_t* Klo_s = smu + s * STAGE_U + ST_KLO;
        const uint32_t vhiB = sb + (uint32_t)(s * STAGE_U + ST_VHI) * 4;

        const bool active = (kb * 64 <= qb * 128 + row0 + 15);

        if (active) {
            // ---- S = Q K^T (3-term split) ----
            float s_acc[8][4];
#pragma unroll
            for (int j = 0; j < 8; j++)
#pragma unroll
                for (int t = 0; t < 4; t++) s_acc[j][t] = 0.f;

#pragma unroll
            for (int ks = 0; ks < 4; ks++) {
#pragma unroll
                for (int fn = 0; fn < 8; fn++) {
                    const int o = (fn * 8 + g) * KPITCH + ks * 8 + 2 * tg;
                    uint2 bh = *(const uint2*)(Khi_s + o);
                    uint2 bl = *(const uint2*)(Klo_s + o);
                    mma_f16(s_acc[fn], qh[ks], bh.x, bh.y);
                    mma_f16(s_acc[fn], qh[ks], bl.x, bl.y);
                    mma_f16(s_acc[fn], ql[ks], bh.x, bh.y);
                }
            }

            // ---- mask + online softmax (base-2) + pack P (hi only) ----
            uint32_t php[8][2];
            const bool diag = (kb >= 2 * qb);
#pragma unroll
            for (int h = 0; h < 2; h++) {
                if (diag) {
                    int row = qb * 128 + row0 + g + 8 * h;
#pragma unroll
                    for (int fn = 0; fn < 8; fn++) {
                        int col = kb * 64 + fn * 8 + 2 * tg;
                        if (col > row)     s_acc[fn][h * 2 + 0] = -1.0e30f;
                        if (col + 1 > row) s_acc[fn][h * 2 + 1] = -1.0e30f;
                    }
                }
                float mx = s_acc[0][h * 2];
#pragma unroll
                for (int fn = 0; fn < 8; fn++) {
                    mx = fmaxf(mx, s_acc[fn][h * 2 + 0]);
                    mx = fmaxf(mx, s_acc[fn][h * 2 + 1]);
                }
                mx = fmaxf(mx, __shfl_xor_sync(0xffffffffu, mx, 1));
                mx = fmaxf(mx, __shfl_xor_sync(0xffffffffu, mx, 2));
                float mn   = fmaxf(m_run[h], mx);
                float corr = exp2f(m_run[h] - mn);
                float rs = 0.f;
#pragma unroll
                for (int fn = 0; fn < 8; fn++) {
                    float p0 = exp2f(s_acc[fn][h * 2 + 0] - mn);
                    float p1 = exp2f(s_acc[fn][h * 2 + 1] - mn);
                    rs += p0 + p1;
                    php[fn][h] = h2u(__floats2half2_rn(p0, p1));
                }
                rs += __shfl_xor_sync(0xffffffffu, rs, 1);
                rs += __shfl_xor_sync(0xffffffffu, rs, 2);
                l_run[h] = l_run[h] * corr + rs;
                m_run[h] = mn;
#pragma unroll
                for (int fn = 0; fn < 8; fn++) {
                    acc_o[fn][h * 2 + 0] *= corr;
                    acc_o[fn][h * 2 + 1] *= corr;
                }
            }

            // ---- O += P V (P hi-only, V hi-only) ----
#pragma unroll
            for (int ks = 0; ks < 4; ks++) {
                uint32_t ahi[4] = { php[2 * ks][0], php[2 * ks][1],
                                    php[2 * ks + 1][0], php[2 * ks + 1][1] };
                const int vrow = ks * 16 + (lane & 15);
                const uint32_t abH = vhiB + (uint32_t)(vrow * VPITCH) * 4;
#pragma unroll
                for (int fn = 0; fn < 8; fn++) {
                    uint2 bh = ldsm_x2_trans(abH + fn * 16);
                    mma_f16(acc_o[fn], ahi, bh.x, bh.y);
                }
            }
        }

        __syncthreads();
        if (kb + 2 < ntiles) ATTN_ISSUE(kb + 2, s);
        CP_COMMIT();
    }
#undef ATTN_ISSUE

    // ---- normalize + write AO as fp16 hi/lo, X-style pair-permutation ----
    // u32 slot within a 16-d group for pair j: j<4 ? 2j : 2(j-4)+1
    // here j = (fn&1)*4 + tg  ->  slot = 2tg + (fn&1); group = fn>>1
    const int bb = bh >> 4, hh = bh & 15;
#pragma unroll
    for (int h = 0; h < 2; h++) {
        float invl = 1.0f / l_run[h];
        int row = qb * 128 + row0 + g + 8 * h;
        size_t rbase = ((size_t)bb * SLEN + row) * (DMODEL / 2) + hh * (DKH / 2);
        uint32_t* dsth = (uint32_t*)g_AOh + rbase;
        uint32_t* dstl = (uint32_t*)g_AOl + rbase;
#pragma unroll
        for (int fn = 0; fn < 8; fn++) {
            float o0 = acc_o[fn][h * 2 + 0] * invl;
            float o1 = acc_o[fn][h * 2 + 1] * invl;
            half2 hi2 = __floats2half2_rn(o0, o1);
            half2 lo2 = __floats2half2_rn(o0 - __low2float(hi2), o1 - __high2float(hi2));
            int slot = ((fn >> 1) << 3) + 2 * tg + (fn & 1);
            dsth[slot] = h2u(hi2);
            dstl[slot] = h2u(lo2);
        }
    }
}

// ---------------- launch -------------------------------------------------------
extern "C" void kernel_launch(void* const* d_in, const int* in_sizes, int n_in,
                              void* d_out, int out_size) {
    const float* q  = (const float*)d_in[0];
    const float* k  = (const float*)d_in[1];
    const float* v  = (const float*)d_in[2];
    // d_in[3] = mask (int32 tril) — causal, applied analytically
    const float* wq = (const float*)d_in[4];
    const float* bq = (const float*)d_in[5];
    const float* wk = (const float*)d_in[6];
    const float* bk = (const float*)d_in[7];
    const float* wv = (const float*)d_in[8];
    const float* bv = (const float*)d_in[9];
    const float* wo = (const float*)d_in[10];
    const float* bo = (const float*)d_in[11];
    float* out = (float*)d_out;

    cudaFuncSetAttribute(qkv_f16_kernel, cudaFuncAttributeMaxDynamicSharedMemorySize, GEMM_SMEM);
    cudaFuncSetAttribute(outproj_f16_kernel, cudaFuncAttributeMaxDynamicSharedMemorySize, GEMM_SMEM);
    cudaFuncSetAttribute(attn_hmma_kernel, cudaFuncAttributeMaxDynamicSharedMemorySize, ATTN_SMEM_BYTES);

    conv_all_kernel<<<7168, 256>>>(q, k, v, wq, wk, wv, wo);

    qkv_f16_kernel<<<dim3(DMODEL / 128, MTOT / 128, 3), 256, GEMM_SMEM>>>(bq, bk, bv);

    attn_hmma_kernel<<<dim3(SLEN / 128, NB * NHEAD), 256, ATTN_SMEM_BYTES>>>();

    outproj_f16_kernel<<<dim3(DMODEL / 128, MTOT / 128), 256, GEMM_SMEM>>>(bo, out);
}

// round 16
// speedup vs baseline: 1.3476x; 1.3476x over previous
#include <cuda_runtime.h>
#include <cuda_fp16.h>
#include <cstdint>

#define SLEN    2048
#define DMODEL  1024
#define NHEAD   16
#define DKH     64
#define NB      4
#define MTOT    (NB * SLEN)     // 8192

// ---------------- scratch (allocation-free: __device__ globals) ----------------
// fp16 Q hi/lo; K hi-only; V hi-only. Layout [B,H,S,64].
// Q is pre-scaled by 0.125*log2(e); Q and K are d-PAIR-PERMUTED; V is natural.
__device__ __half g_Qh[(size_t)NB * NHEAD * SLEN * DKH];
__device__ __half g_Ql[(size_t)NB * NHEAD * SLEN * DKH];
__device__ __half g_Kh[(size_t)NB * NHEAD * SLEN * DKH];
__device__ __half g_Vh[(size_t)NB * NHEAD * SLEN * DKH];

// pre-converted tf32 operands, pair-permuted within each 8-k group:
// u32 order per group = [k0,k4,k1,k5,k2,k6,k3,k7]
__device__ uint32_t g_Xt[(size_t)3 * MTOT * DMODEL];     // q,k,v inputs
__device__ uint32_t g_Wt[(size_t)4 * DMODEL * DMODEL];   // wq,wk,wv,wo
__device__ uint32_t g_AOt[(size_t)MTOT * DMODEL];        // attn out, tf32 permuted

// ---------------- helpers ------------------------------------------------------
__device__ __forceinline__ uint32_t f2tf32(float f) {
    uint32_t u;
    asm("cvt.rna.tf32.f32 %0, %1;" : "=r"(u) : "f"(f));
    return u;
}

__device__ __forceinline__ void mma_tf32(float c[4], const uint32_t a[4], const uint32_t b[2]) {
    asm volatile(
        "mma.sync.aligned.m16n8k8.row.col.f32.tf32.tf32.f32 "
        "{%0,%1,%2,%3}, {%4,%5,%6,%7}, {%8,%9}, {%0,%1,%2,%3};"
        : "+f"(c[0]), "+f"(c[1]), "+f"(c[2]), "+f"(c[3])
        : "r"(a[0]), "r"(a[1]), "r"(a[2]), "r"(a[3]), "r"(b[0]), "r"(b[1]));
}

__device__ __forceinline__ uint32_t smem_u32(const void* p) {
    uint32_t a;
    asm("{ .reg .u64 t; cvta.to.shared.u64 t, %1; cvt.u32.u64 %0, t; }" : "=r"(a) : "l"(p));
    return a;
}

__device__ __forceinline__ void cp16(uint32_t dst, const void* src) {
    asm volatile("cp.async.cg.shared.global [%0], [%1], 16;" :: "r"(dst), "l"(src));
}
#define CP_COMMIT() asm volatile("cp.async.commit_group;")
#define CP_WAIT(n)  asm volatile("cp.async.wait_group %0;" :: "n"(n))

__device__ __forceinline__ uint2 ldsm_x2_trans(uint32_t addr) {
    uint2 r;
    asm volatile("ldmatrix.sync.aligned.m8n8.x2.trans.shared.b16 {%0,%1}, [%2];"
                 : "=r"(r.x), "=r"(r.y) : "r"(addr));
    return r;
}

__device__ __forceinline__ uint32_t h2u(half2 h) {
    return *reinterpret_cast<uint32_t*>(&h);
}

__device__ __forceinline__ void mma_f16(float c[4], const uint32_t a[4],
                                        uint32_t b0, uint32_t b1) {
    asm volatile(
        "mma.sync.aligned.m16n8k16.row.col.f32.f16.f16.f32 "
        "{%0,%1,%2,%3}, {%4,%5,%6,%7}, {%8,%9}, {%0,%1,%2,%3};"
        : "+f"(c[0]), "+f"(c[1]), "+f"(c[2]), "+f"(c[3])
        : "r"(a[0]), "r"(a[1]), "r"(a[2]), "r"(a[3]), "r"(b0), "r"(b1));
}

// ---------------- fused tf32 pre-convert (all 7 tensors, one launch) -----------
__global__ __launch_bounds__(256) void conv_all_kernel(
    const float* __restrict__ q, const float* __restrict__ k, const float* __restrict__ v,
    const float* __restrict__ wq, const float* __restrict__ wk,
    const float* __restrict__ wv, const float* __restrict__ wo)
{
    int b = blockIdx.x;
    const float* src;
    uint32_t* dst;
    int i;
    if (b < 12288) {
        int sel = b >> 12;
        src = (sel == 0) ? q : (sel == 1) ? k : v;
        dst = g_Xt + (size_t)sel * MTOT * DMODEL;
        i = (b & 4095) * 256 + threadIdx.x;
    } else {
        int sel = (b - 12288) >> 9;
        src = (sel == 0) ? wq : (sel == 1) ? wk : (sel == 2) ? wv : wo;
        dst = g_Wt + (size_t)sel * DMODEL * DMODEL;
        i = ((b - 12288) & 511) * 256 + threadIdx.x;
    }
    const float4* s4 = (const float4*)src;
    uint4* d4 = (uint4*)dst;
    float4 v0 = s4[2 * i];
    float4 v1 = s4[2 * i + 1];
    uint4 o0, o1;
    o0.x = f2tf32(v0.x); o0.y = f2tf32(v1.x);   // k0,k4
    o0.z = f2tf32(v0.y); o0.w = f2tf32(v1.y);   // k1,k5
    o1.x = f2tf32(v0.z); o1.y = f2tf32(v1.z);   // k2,k6
    o1.z = f2tf32(v0.w); o1.w = f2tf32(v1.w);   // k3,k7
    d4[2 * i]     = o0;
    d4[2 * i + 1] = o1;
}

// ======================= tf32 tensor-core GEMM (R9 config) =====================
// 128x128 CTA tile, 256 threads (2m x 4n warps, warp tile 64x32), BK=32, 2-stage.
#define BK2 32
#define P40 40
#define STAGEU (128 * P40)                    // u32 per operand per stage
#define GEMM_SMEM (2 * 2 * STAGEU * 4)        // 81920 bytes

__device__ __forceinline__ void gemm_tf32_main(const uint32_t* __restrict__ X,
                                               const uint32_t* __restrict__ W,
                                               int m0, int n0,
                                               float acc[4][4][4]) {
    extern __shared__ uint32_t su[];
    const int tid  = threadIdx.x;
    const int lane = tid & 31, warp = tid >> 5;
    const int wm = warp >> 2, wn = warp & 3;
    const int g  = lane >> 2, tg = lane & 3;

    const uint32_t sb = smem_u32(su);

#define ISSUE_TILE(kt, s)                                                           \
    do {                                                                            \
        uint32_t _b = sb + ((uint32_t)(s) * 2 * STAGEU) * 4u;                       \
        _Pragma("unroll")                                                           \
        for (int _j = 0; _j < 4; _j++) {                                            \
            int _seg = tid + _j * 256;                                              \
            int _row = _seg >> 3;                                                   \
            int _ch  = _seg & 7;                                                    \
            uint32_t _off = (uint32_t)(_row * P40 * 4 + _ch * 16);                  \
            cp16(_b + _off,                                                         \
                 (const char*)(X + (size_t)(m0 + _row) * DMODEL + (kt) * BK2) + _ch * 16); \
            cp16(_b + (uint32_t)(STAGEU * 4) + _off,                                \
                 (const char*)(W + (size_t)(n0 + _row) * DMODEL + (kt) * BK2) + _ch * 16); \
        }                                                                           \
    } while (0)

    const int NT = DMODEL / BK2;              // 32
    ISSUE_TILE(0, 0); CP_COMMIT();
    ISSUE_TILE(1, 1); CP_COMMIT();

    for (int kt = 0; kt < NT; kt++) {
        CP_WAIT(1);
        __syncthreads();

        const int s = kt & 1;
        const uint32_t* Asb = su + s * 2 * STAGEU;
        const uint32_t* Bsb = Asb + STAGEU;

#pragma unroll
        for (int kg = 0; kg < 4; kg++) {
            const int colb = kg * 8 + 2 * tg;
            uint32_t a[4][4], b[4][2];
#pragma unroll
            for (int fm = 0; fm < 4; fm++) {
                const int r = wm * 64 + fm * 16 + g;
                uint2 t0 = *(const uint2*)(Asb + r * P40 + colb);
                uint2 t1 = *(const uint2*)(Asb + (r + 8) * P40 + colb);
                a[fm][0] = t0.x; a[fm][2] = t0.y;
                a[fm][1] = t1.x; a[fm][3] = t1.y;
            }
#pragma unroll
            for (int fn = 0; fn < 4; fn++) {
                const int r = wn * 32 + fn * 8 + g;
                uint2 t = *(const uint2*)(Bsb + r * P40 + colb);
                b[fn][0] = t.x; b[fn][1] = t.y;
            }
#pragma unroll
            for (int fm = 0; fm < 4; fm++)
#pragma unroll
                for (int fn = 0; fn < 4; fn++)
                    mma_tf32(acc[fm][fn], a[fm], b[fn]);
        }

        __syncthreads();
        if (kt + 2 < NT) ISSUE_TILE(kt + 2, s);
        CP_COMMIT();
    }
#undef ISSUE_TILE
}

// ---------------- QKV projection -> fp16 (Q hi/lo, K hi, V hi) -----------------
#define QSCALE 0.180336880f

__global__ __launch_bounds__(256, 2) void qkv_tf32_kernel(
    const float* __restrict__ bq, const float* __restrict__ bk, const float* __restrict__ bv)
{
    const int z = blockIdx.z;
    const uint32_t* X = g_Xt + (size_t)z * MTOT * DMODEL;
    const uint32_t* W = g_Wt + (size_t)z * DMODEL * DMODEL;
    const float* Bb   = (z == 0) ? bq : (z == 1) ? bk : bv;
    __half* Hh        = (z == 0) ? g_Qh : (z == 1) ? g_Kh : g_Vh;
    const float scale = (z == 0) ? QSCALE : 1.0f;

    const int m0 = blockIdx.y * 128, n0 = blockIdx.x * 128;
    float acc[4][4][4];
#pragma unroll
    for (int i = 0; i < 4; i++)
#pragma unroll
        for (int j = 0; j < 4; j++)
#pragma unroll
            for (int t = 0; t < 4; t++) acc[i][j][t] = 0.f;

    gemm_tf32_main(X, W, m0, n0, acc);

    const int tid  = threadIdx.x;
    const int lane = tid & 31, warp = tid >> 5;
    const int wm = warp >> 2, wn = warp & 3;
    const int g  = lane >> 2, tg = lane & 3;

#pragma unroll
    for (int fn = 0; fn < 4; fn++) {
        const int n  = n0 + wn * 32 + fn * 8 + 2 * tg;
        const int hh = n >> 6, dd = n & 63;
        int ddw;
        if (z < 2) {
            int kk  = dd >> 1;
            int grp = kk >> 3, pig = kk & 7;
            int pp  = ((pig & 3) << 1) | (pig >> 2);
            ddw = (grp * 8 + pp) * 2;
        } else {
            ddw = dd;
        }
        const float b0 = Bb[n], b1 = Bb[n + 1];
#pragma unroll
        for (int fm = 0; fm < 4; fm++) {
#pragma unroll
            for (int half_ = 0; half_ < 2; half_++) {
                const int m  = m0 + wm * 64 + fm * 16 + g + half_ * 8;
                const int bb = m >> 11;
                const int ss = m & (SLEN - 1);
                float v0 = (acc[fm][fn][half_ * 2 + 0] + b0) * scale;
                float v1 = (acc[fm][fn][half_ * 2 + 1] + b1) * scale;
                half2 hi = __floats2half2_rn(v0, v1);
                size_t idx = (((size_t)bb * NHEAD + hh) * SLEN + ss) * DKH + ddw;
                *(half2*)(Hh + idx) = hi;
                if (z == 0) {
                    half2 lo = __floats2half2_rn(v0 - __low2float(hi), v1 - __high2float(hi));
                    *(half2*)(g_Ql + idx) = lo;
                }
            }
        }
    }
}

// ---------------- output projection -------------------------------------------
__global__ __launch_bounds__(256, 2) void outproj_tf32_kernel(
    const float* __restrict__ Bb, float* __restrict__ Out)
{
    const uint32_t* W = g_Wt + (size_t)3 * DMODEL * DMODEL;
    const int m0 = blockIdx.y * 128, n0 = blockIdx.x * 128;
    float acc[4][4][4];
#pragma unroll
    for (int i = 0; i < 4; i++)
#pragma unroll
        for (int j = 0; j < 4; j++)
#pragma unroll
            for (int t = 0; t < 4; t++) acc[i][j][t] = 0.f;

    gemm_tf32_main(g_AOt, W, m0, n0, acc);

    const int tid  = threadIdx.x;
    const int lane = tid & 31, warp = tid >> 5;
    const int wm = warp >> 2, wn = warp & 3;
    const int g  = lane >> 2, tg = lane & 3;

#pragma unroll
    for (int fn = 0; fn < 4; fn++) {
        const int n = n0 + wn * 32 + fn * 8 + 2 * tg;
        const float b0 = Bb[n], b1 = Bb[n + 1];
#pragma unroll
        for (int fm = 0; fm < 4; fm++) {
#pragma unroll
            for (int half_ = 0; half_ < 2; half_++) {
                const int m = m0 + wm * 64 + fm * 16 + g + half_ * 8;
                *(float2*)(Out + (size_t)m * DMODEL + n) =
                    make_float2(acc[fm][fn][half_ * 2 + 0] + b0,
                                acc[fm][fn][half_ * 2 + 1] + b1);
            }
        }
    }
}

// ===== Flash attention: 128-row tiles, 2-stage, K hi-only, P hi-only, V hi-only
// smem per stage (u32): K hi [64][40], V hi [64][36]
#define KPITCH 40
#define VPITCH 36
#define ST_KHI 0
#define ST_VHI 2560
#define STAGE_U 4864
#define ATTN_SMEM_BYTES (2 * STAGE_U * 4)     // 38912

__global__ __launch_bounds__(256, 2) void attn_hmma_kernel() {
    extern __shared__ uint32_t smu[];

    const int qb = 15 - blockIdx.x;            // long CTAs first
    const int bh = blockIdx.y;
    const size_t base = (size_t)bh * SLEN * DKH;
    const __half* Khg = g_Kh + base;
    const __half* Vhg = g_Vh + base;

    const int tid  = threadIdx.x;
    const int lane = tid & 31, warp = tid >> 5;
    const int g  = lane >> 2, tg = lane & 3;
    const int row0 = warp * 16;
    const uint32_t sb = smem_u32(smu);

    // per-tile loads: K hi 512 cp16 + V hi 512 cp16 -> 4 per thread
#define ATTN_ISSUE(kb_, s_)                                                         \
    do {                                                                            \
        _Pragma("unroll")                                                           \
        for (int _j = 0; _j < 2; _j++) {                                            \
            int _t = tid + _j * 256;          /* 0..511 */                          \
            int _row = _t >> 3;                                                     \
            int _c7 = _t & 7;                                                       \
            const __half* _ks = Khg + (size_t)((kb_) * 64 + _row) * DKH + _c7 * 8;  \
            cp16(sb + (uint32_t)((s_) * STAGE_U + ST_KHI                            \
                                  + _row * KPITCH + _c7 * 4) * 4, _ks);             \
            const __half* _vs = Vhg + (size_t)((kb_) * 64 + _row) * DKH + _c7 * 8;  \
            cp16(sb + (uint32_t)((s_) * STAGE_U + ST_VHI                            \
                                  + _row * VPITCH + _c7 * 4) * 4, _vs);             \
        }                                                                           \
    } while (0)

    ATTN_ISSUE(0, 0); CP_COMMIT();
    ATTN_ISSUE(1, 1); CP_COMMIT();

    // ---- Q fragments -> registers (pair-permuted global, LDG.64) ----
    uint32_t qh[4][4], ql[4][4];
    {
        const uint32_t* Qg  = (const uint32_t*)g_Qh + (base >> 1)
                              + (size_t)(qb * 128 + row0 + g) * 32;
        const uint32_t* Qgl = (const uint32_t*)g_Ql + (base >> 1)
                              + (size_t)(qb * 128 + row0 + g) * 32;
#pragma unroll
        for (int ks = 0; ks < 4; ks++) {
            uint2 a0 = *(const uint2*)(Qg + ks * 8 + 2 * tg);
            uint2 a1 = *(const uint2*)(Qg + 8 * 32 + ks * 8 + 2 * tg);
            qh[ks][0] = a0.x; qh[ks][1] = a1.x; qh[ks][2] = a0.y; qh[ks][3] = a1.y;
            uint2 b0 = *(const uint2*)(Qgl + ks * 8 + 2 * tg);
            uint2 b1 = *(const uint2*)(Qgl + 8 * 32 + ks * 8 + 2 * tg);
            ql[ks][0] = b0.x; ql[ks][1] = b1.x; ql[ks][2] = b0.y; ql[ks][3] = b1.y;
        }
    }

    float acc_o[8][4];
#pragma unroll
    for (int j = 0; j < 8; j++)
#pragma unroll
        for (int t = 0; t < 4; t++) acc_o[j][t] = 0.f;
    float m_run[2] = {-1.0e30f, -1.0e30f};
    float l_run[2] = {0.f, 0.f};

    const int ntiles = 2 * (qb + 1);
    for (int kb = 0; kb < ntiles; kb++) {
        CP_WAIT(1);
        __syncthreads();

        const int s = kb & 1;
        const uint32_t* Khi_s = smu + s * STAGE_U + ST_KHI;
        const uint32_t vhiB = sb + (uint32_t)(s * STAGE_U + ST_VHI) * 4;

        const bool active = (kb * 64 <= qb * 128 + row0 + 15);

        if (active) {
            // ---- S = Q K^T (2-term: qh*kh + ql*kh; K fp16-rounded) ----
            float s_acc[8][4];
#pragma unroll
            for (int j = 0; j < 8; j++)
#pragma unroll
                for (int t = 0; t < 4; t++) s_acc[j][t] = 0.f;

#pragma unroll
            for (int ks = 0; ks < 4; ks++) {
#pragma unroll
                for (int fn = 0; fn < 8; fn++) {
                    const int o = (fn * 8 + g) * KPITCH + ks * 8 + 2 * tg;
                    uint2 bh = *(const uint2*)(Khi_s + o);
                    mma_f16(s_acc[fn], qh[ks], bh.x, bh.y);
                    mma_f16(s_acc[fn], ql[ks], bh.x, bh.y);
                }
            }

            // ---- mask + online softmax (base-2) + pack P (hi only) ----
            uint32_t php[8][2];
            const bool diag = (kb >= 2 * qb);
#pragma unroll
            for (int h = 0; h < 2; h++) {
                if (diag) {
                    int row = qb * 128 + row0 + g + 8 * h;
#pragma unroll
                    for (int fn = 0; fn < 8; fn++) {
                        int col = kb * 64 + fn * 8 + 2 * tg;
                        if (col > row)     s_acc[fn][h * 2 + 0] = -1.0e30f;
                        if (col + 1 > row) s_acc[fn][h * 2 + 1] = -1.0e30f;
                    }
                }
                float mx = s_acc[0][h * 2];
#pragma unroll
                for (int fn = 0; fn < 8; fn++) {
                    mx = fmaxf(mx, s_acc[fn][h * 2 + 0]);
                    mx = fmaxf(mx, s_acc[fn][h * 2 + 1]);
                }
                mx = fmaxf(mx, __shfl_xor_sync(0xffffffffu, mx, 1));
                mx = fmaxf(mx, __shfl_xor_sync(0xffffffffu, mx, 2));
                float mn   = fmaxf(m_run[h], mx);
                float corr = exp2f(m_run[h] - mn);
                float rs = 0.f;
#pragma unroll
                for (int fn = 0; fn < 8; fn++) {
                    float p0 = exp2f(s_acc[fn][h * 2 + 0] - mn);
                    float p1 = exp2f(s_acc[fn][h * 2 + 1] - mn);
                    rs += p0 + p1;
                    php[fn][h] = h2u(__floats2half2_rn(p0, p1));
                }
                rs += __shfl_xor_sync(0xffffffffu, rs, 1);
                rs += __shfl_xor_sync(0xffffffffu, rs, 2);
                l_run[h] = l_run[h] * corr + rs;
                m_run[h] = mn;
#pragma unroll
                for (int fn = 0; fn < 8; fn++) {
                    acc_o[fn][h * 2 + 0] *= corr;
                    acc_o[fn][h * 2 + 1] *= corr;
                }
            }

            // ---- O += P V (P hi-only, V hi-only) ----
#pragma unroll
            for (int ks = 0; ks < 4; ks++) {
                uint32_t ahi[4] = { php[2 * ks][0], php[2 * ks][1],
                                    php[2 * ks + 1][0], php[2 * ks + 1][1] };
                const int vrow = ks * 16 + (lane & 15);
                const uint32_t abH = vhiB + (uint32_t)(vrow * VPITCH) * 4;
#pragma unroll
                for (int fn = 0; fn < 8; fn++) {
                    uint2 bh = ldsm_x2_trans(abH + fn * 16);
                    mma_f16(acc_o[fn], ahi, bh.x, bh.y);
                }
            }
        }

        __syncthreads();
        if (kb + 2 < ntiles) ATTN_ISSUE(kb + 2, s);
        CP_COMMIT();
    }
#undef ATTN_ISSUE

    // ---- normalize + write tf32 pair-permuted AO (R9 permutation) ----
    const int bb = bh >> 4, hh = bh & 15;
    const int kk0 = 2 * tg, kk1 = 2 * tg + 1;
    const int p0 = ((kk0 & 3) << 1) | (kk0 >> 2);
    const int p1 = ((kk1 & 3) << 1) | (kk1 >> 2);
#pragma unroll
    for (int h = 0; h < 2; h++) {
        float invl = 1.0f / l_run[h];
        int row = qb * 128 + row0 + g + 8 * h;
        uint32_t* dst = g_AOt + ((size_t)bb * SLEN + row) * DMODEL + hh * DKH;
#pragma unroll
        for (int fn = 0; fn < 8; fn++) {
            dst[fn * 8 + p0] = f2tf32(acc_o[fn][h * 2 + 0] * invl);
            dst[fn * 8 + p1] = f2tf32(acc_o[fn][h * 2 + 1] * invl);
        }
    }
}

// ---------------- launch -------------------------------------------------------
extern "C" void kernel_launch(void* const* d_in, const int* in_sizes, int n_in,
                              void* d_out, int out_size) {
    const float* q  = (const float*)d_in[0];
    const float* k  = (const float*)d_in[1];
    const float* v  = (const float*)d_in[2];
    // d_in[3] = mask (int32 tril) — causal, applied analytically
    const float* wq = (const float*)d_in[4];
    const float* bq = (const float*)d_in[5];
    const float* wk = (const float*)d_in[6];
    const float* bk = (const float*)d_in[7];
    const float* wv = (const float*)d_in[8];
    const float* bv = (const float*)d_in[9];
    const float* wo = (const float*)d_in[10];
    const float* bo = (const float*)d_in[11];
    float* out = (float*)d_out;

    cudaFuncSetAttribute(qkv_tf32_kernel, cudaFuncAttributeMaxDynamicSharedMemorySize, GEMM_SMEM);
    cudaFuncSetAttribute(outproj_tf32_kernel, cudaFuncAttributeMaxDynamicSharedMemorySize, GEMM_SMEM);
    cudaFuncSetAttribute(attn_hmma_kernel, cudaFuncAttributeMaxDynamicSharedMemorySize, ATTN_SMEM_BYTES);

    conv_all_kernel<<<14336, 256>>>(q, k, v, wq, wk, wv, wo);

    qkv_tf32_kernel<<<dim3(DMODEL / 128, MTOT / 128, 3), 256, GEMM_SMEM>>>(bq, bk, bv);

    attn_hmma_kernel<<<dim3(SLEN / 128, NB * NHEAD), 256, ATTN_SMEM_BYTES>>>();

    outproj_tf32_kernel<<<dim3(DMODEL / 128, MTOT / 128), 256, GEMM_SMEM>>>(bo, out);
}

// round 17
// speedup vs baseline: 1.9161x; 1.4219x over previous
#include <cuda_runtime.h>
#include <cuda_fp16.h>
#include <cstdint>

#define SLEN    2048
#define DMODEL  1024
#define NHEAD   16
#define DKH     64
#define NB      4
#define MTOT    (NB * SLEN)     // 8192

// ---------------- scratch (allocation-free: __device__ globals) ----------------
// fp16 Q hi/lo; K hi-only; V hi-only. Layout [B,H,S,64].
// Q is pre-scaled by 0.125*log2(e); Q and K are d-PAIR-PERMUTED; V is natural.
__device__ __half g_Qh[(size_t)NB * NHEAD * SLEN * DKH];
__device__ __half g_Ql[(size_t)NB * NHEAD * SLEN * DKH];
__device__ __half g_Kh[(size_t)NB * NHEAD * SLEN * DKH];
__device__ __half g_Vh[(size_t)NB * NHEAD * SLEN * DKH];

// fp16 GEMM operands (hi only), pair-permuted per 16-d group on u32 pairs:
// u32 slot order per 8-u32 group = [pr0,pr4,pr1,pr5,pr2,pr6,pr3,pr7]
__device__ __half g_Xh[(size_t)3 * MTOT * DMODEL];   // q,k,v inputs
__device__ __half g_Wh[(size_t)4 * DMODEL * DMODEL]; // wq,wk,wv,wo
__device__ __half g_AOh[(size_t)MTOT * DMODEL];      // attn out

// ---------------- helpers ------------------------------------------------------
__device__ __forceinline__ uint32_t smem_u32(const void* p) {
    uint32_t a;
    asm("{ .reg .u64 t; cvta.to.shared.u64 t, %1; cvt.u32.u64 %0, t; }" : "=r"(a) : "l"(p));
    return a;
}

__device__ __forceinline__ void cp16(uint32_t dst, const void* src) {
    asm volatile("cp.async.cg.shared.global [%0], [%1], 16;" :: "r"(dst), "l"(src));
}
#define CP_COMMIT() asm volatile("cp.async.commit_group;")
#define CP_WAIT(n)  asm volatile("cp.async.wait_group %0;" :: "n"(n))

__device__ __forceinline__ uint2 ldsm_x2_trans(uint32_t addr) {
    uint2 r;
    asm volatile("ldmatrix.sync.aligned.m8n8.x2.trans.shared.b16 {%0,%1}, [%2];"
                 : "=r"(r.x), "=r"(r.y) : "r"(addr));
    return r;
}

__device__ __forceinline__ uint32_t h2u(half2 h) {
    return *reinterpret_cast<uint32_t*>(&h);
}

__device__ __forceinline__ void mma_f16(float c[4], const uint32_t a[4],
                                        uint32_t b0, uint32_t b1) {
    asm volatile(
        "mma.sync.aligned.m16n8k16.row.col.f32.f16.f16.f32 "
        "{%0,%1,%2,%3}, {%4,%5,%6,%7}, {%8,%9}, {%0,%1,%2,%3};"
        : "+f"(c[0]), "+f"(c[1]), "+f"(c[2]), "+f"(c[3])
        : "r"(a[0]), "r"(a[1]), "r"(a[2]), "r"(a[3]), "r"(b0), "r"(b1));
}

// ---------------- fused fp16 pre-convert (all 7 tensors, one launch) -----------
// Each thread handles one 16-float group: writes 8 hi u32 (pair-permuted).
__global__ __launch_bounds__(256) void conv_all_kernel(
    const float* __restrict__ q, const float* __restrict__ k, const float* __restrict__ v,
    const float* __restrict__ wq, const float* __restrict__ wk,
    const float* __restrict__ wv, const float* __restrict__ wo)
{
    int b = blockIdx.x;
    const float* src;
    __half* dh;
    size_t i;
    if (b < 6144) {
        int sel = b >> 11;
        src = (sel == 0) ? q : (sel == 1) ? k : v;
        dh = g_Xh + (size_t)sel * MTOT * DMODEL;
        i = (size_t)(b & 2047) * 256 + threadIdx.x;
    } else {
        int sel = (b - 6144) >> 8;
        src = (sel == 0) ? wq : (sel == 1) ? wk : (sel == 2) ? wv : wo;
        dh = g_Wh + (size_t)sel * DMODEL * DMODEL;
        i = (size_t)((b - 6144) & 255) * 256 + threadIdx.x;
    }
    const float4* s4 = (const float4*)src + 4 * i;
    float4 v0 = s4[0], v1 = s4[1], v2 = s4[2], v3 = s4[3];
    float px[16] = { v0.x, v0.y, v0.z, v0.w, v1.x, v1.y, v1.z, v1.w,
                     v2.x, v2.y, v2.z, v2.w, v3.x, v3.y, v3.z, v3.w };
    uint32_t hu[8];
#pragma unroll
    for (int j = 0; j < 8; j++)
        hu[j] = h2u(__floats2half2_rn(px[2 * j], px[2 * j + 1]));
    uint4* oh = (uint4*)dh + 2 * i;
    oh[0] = make_uint4(hu[0], hu[4], hu[1], hu[5]);
    oh[1] = make_uint4(hu[2], hu[6], hu[3], hu[7]);
}

// ======================= 1-term fp16 tensor-core GEMM ==========================
// 128x128 CTA tile, 256 threads (2m x 4n warps, warp tile 64x32), BK=32, 2-stage.
// smem arrays per stage: Ahi, Bhi each [128][24] u32 (16 used per row).
#define BK2 32
#define P24 24
#define HS_U (128 * P24)                      // 3072 u32 per array
#define STG_U (2 * HS_U)                      // 6144 u32 per stage
#define GEMM_SMEM (2 * STG_U * 4)             // 49152 bytes

__device__ __forceinline__ void gemm_f16_main(
    const uint32_t* __restrict__ Xh, const uint32_t* __restrict__ Wh,
    int m0, int n0, float acc[4][4][4])
{
    extern __shared__ uint32_t su[];
    const int tid  = threadIdx.x;
    const int lane = tid & 31, warp = tid >> 5;
    const int wm = warp >> 2, wn = warp & 3;
    const int g  = lane >> 2, tg = lane & 3;
    const uint32_t sb = smem_u32(su);

    // per thread 4 cp16 per stage: 2 arrays x 128 rows x 4 chunks = 1024
#define ISSUE_TILE(kt, s)                                                           \
    do {                                                                            \
        _Pragma("unroll")                                                           \
        for (int _j = 0; _j < 4; _j++) {                                            \
            int _seg = tid + _j * 256;                                              \
            int _arr = _seg >> 9;                                                   \
            int _w   = _seg & 511;                                                  \
            int _row = _w >> 2;                                                     \
            int _ch  = _w & 3;                                                      \
            const uint32_t* _p = (_arr == 0) ? Xh : Wh;                             \
            int _rb = (_arr == 0) ? m0 : n0;                                        \
            cp16(sb + (uint32_t)((s) * STG_U + _arr * HS_U + _row * P24 + _ch * 4) * 4, \
                 _p + (size_t)(_rb + _row) * 512 + (kt) * 16 + _ch * 4);            \
        }                                                                           \
    } while (0)

    const int NT = DMODEL / BK2;              // 32
    ISSUE_TILE(0, 0); CP_COMMIT();
    ISSUE_TILE(1, 1); CP_COMMIT();

    for (int kt = 0; kt < NT; kt++) {
        CP_WAIT(1);
        __syncthreads();

        const int s = kt & 1;
        const uint32_t* Ah = su + s * STG_U;
        const uint32_t* Bh = Ah + HS_U;

#pragma unroll
        for (int s16 = 0; s16 < 2; s16++) {
            const int colb = s16 * 8 + 2 * tg;
            uint32_t b[4][2];
#pragma unroll
            for (int fn = 0; fn < 4; fn++) {
                uint2 t = *(const uint2*)(Bh + (wn * 32 + fn * 8 + g) * P24 + colb);
                b[fn][0] = t.x; b[fn][1] = t.y;
            }
#pragma unroll
            for (int fm = 0; fm < 4; fm++) {
                const int rr = (wm * 64 + fm * 16 + g) * P24 + colb;
                uint2 h0 = *(const uint2*)(Ah + rr);
                uint2 h1 = *(const uint2*)(Ah + rr + 8 * P24);
                uint32_t ahi[4] = { h0.x, h1.x, h0.y, h1.y };
#pragma unroll
                for (int fn = 0; fn < 4; fn++)
                    mma_f16(acc[fm][fn], ahi, b[fn][0], b[fn][1]);
            }
        }

        __syncthreads();
        if (kt + 2 < NT) ISSUE_TILE(kt + 2, s);
        CP_COMMIT();
    }
#undef ISSUE_TILE
}

// ---------------- QKV projection -> fp16 (Q hi/lo, K hi, V hi) -----------------
#define QSCALE 0.180336880f

__global__ __launch_bounds__(256, 2) void qkv_f16_kernel(
    const float* __restrict__ bq, const float* __restrict__ bk, const float* __restrict__ bv)
{
    const int z = blockIdx.z;
    const uint32_t* Xh = (const uint32_t*)g_Xh + (size_t)z * MTOT * DMODEL / 2;
    const uint32_t* Wh = (const uint32_t*)g_Wh + (size_t)z * DMODEL * DMODEL / 2;
    const float* Bb   = (z == 0) ? bq : (z == 1) ? bk : bv;
    __half* Hh        = (z == 0) ? g_Qh : (z == 1) ? g_Kh : g_Vh;
    const float scale = (z == 0) ? QSCALE : 1.0f;

    const int m0 = blockIdx.y * 128, n0 = blockIdx.x * 128;
    float acc[4][4][4];
#pragma unroll
    for (int i = 0; i < 4; i++)
#pragma unroll
        for (int j = 0; j < 4; j++)
#pragma unroll
            for (int t = 0; t < 4; t++) acc[i][j][t] = 0.f;

    gemm_f16_main(Xh, Wh, m0, n0, acc);

    const int tid  = threadIdx.x;
    const int lane = tid & 31, warp = tid >> 5;
    const int wm = warp >> 2, wn = warp & 3;
    const int g  = lane >> 2, tg = lane & 3;

#pragma unroll
    for (int fn = 0; fn < 4; fn++) {
        const int n  = n0 + wn * 32 + fn * 8 + 2 * tg;
        const int hh = n >> 6, dd = n & 63;
        int ddw;
        if (z < 2) {
            int kk  = dd >> 1;
            int grp = kk >> 3, pig = kk & 7;
            int pp  = ((pig & 3) << 1) | (pig >> 2);
            ddw = (grp * 8 + pp) * 2;
        } else {
            ddw = dd;
        }
        const float b0 = Bb[n], b1 = Bb[n + 1];
#pragma unroll
        for (int fm = 0; fm < 4; fm++) {
#pragma unroll
            for (int half_ = 0; half_ < 2; half_++) {
                const int m  = m0 + wm * 64 + fm * 16 + g + half_ * 8;
                const int bb = m >> 11;
                const int ss = m & (SLEN - 1);
                float v0 = (acc[fm][fn][half_ * 2 + 0] + b0) * scale;
                float v1 = (acc[fm][fn][half_ * 2 + 1] + b1) * scale;
                half2 hi = __floats2half2_rn(v0, v1);
                size_t idx = (((size_t)bb * NHEAD + hh) * SLEN + ss) * DKH + ddw;
                *(half2*)(Hh + idx) = hi;
                if (z == 0) {
                    half2 lo = __floats2half2_rn(v0 - __low2float(hi), v1 - __high2float(hi));
                    *(half2*)(g_Ql + idx) = lo;
                }
            }
        }
    }
}

// ---------------- output projection -------------------------------------------
__global__ __launch_bounds__(256, 2) void outproj_f16_kernel(
    const float* __restrict__ Bb, float* __restrict__ Out)
{
    const uint32_t* Wh = (const uint32_t*)g_Wh + (size_t)3 * DMODEL * DMODEL / 2;
    const int m0 = blockIdx.y * 128, n0 = blockIdx.x * 128;
    float acc[4][4][4];
#pragma unroll
    for (int i = 0; i < 4; i++)
#pragma unroll
        for (int j = 0; j < 4; j++)
#pragma unroll
            for (int t = 0; t < 4; t++) acc[i][j][t] = 0.f;

    gemm_f16_main((const uint32_t*)g_AOh, Wh, m0, n0, acc);

    const int tid  = threadIdx.x;
    const int lane = tid & 31, warp = tid >> 5;
    const int wm = warp >> 2, wn = warp & 3;
    const int g  = lane >> 2, tg = lane & 3;

#pragma unroll
    for (int fn = 0; fn < 4; fn++) {
        const int n = n0 + wn * 32 + fn * 8 + 2 * tg;
        const float b0 = Bb[n], b1 = Bb[n + 1];
#pragma unroll
        for (int fm = 0; fm < 4; fm++) {
#pragma unroll
            for (int half_ = 0; half_ < 2; half_++) {
                const int m = m0 + wm * 64 + fm * 16 + g + half_ * 8;
                *(float2*)(Out + (size_t)m * DMODEL + n) =
                    make_float2(acc[fm][fn][half_ * 2 + 0] + b0,
                                acc[fm][fn][half_ * 2 + 1] + b1);
            }
        }
    }
}

// ===== Flash attention: 128-row tiles, 2-stage, K hi-only, P hi-only, V hi-only
// smem per stage (u32): K hi [64][40], V hi [64][36]
#define KPITCH 40
#define VPITCH 36
#define ST_KHI 0
#define ST_VHI 2560
#define STAGE_U 4864
#define ATTN_SMEM_BYTES (2 * STAGE_U * 4)     // 38912

__global__ __launch_bounds__(256, 2) void attn_hmma_kernel() {
    extern __shared__ uint32_t smu[];

    const int qb = 15 - blockIdx.x;            // long CTAs first
    const int bh = blockIdx.y;
    const size_t base = (size_t)bh * SLEN * DKH;
    const __half* Khg = g_Kh + base;
    const __half* Vhg = g_Vh + base;

    const int tid  = threadIdx.x;
    const int lane = tid & 31, warp = tid >> 5;
    const int g  = lane >> 2, tg = lane & 3;
    const int row0 = warp * 16;
    const uint32_t sb = smem_u32(smu);

#define ATTN_ISSUE(kb_, s_)                                                         \
    do {                                                                            \
        _Pragma("unroll")                                                           \
        for (int _j = 0; _j < 2; _j++) {                                            \
            int _t = tid + _j * 256;          /* 0..511 */                          \
            int _row = _t >> 3;                                                     \
            int _c7 = _t & 7;                                                       \
            const __half* _ks = Khg + (size_t)((kb_) * 64 + _row) * DKH + _c7 * 8;  \
            cp16(sb + (uint32_t)((s_) * STAGE_U + ST_KHI                            \
                                  + _row * KPITCH + _c7 * 4) * 4, _ks);             \
            const __half* _vs = Vhg + (size_t)((kb_) * 64 + _row) * DKH + _c7 * 8;  \
            cp16(sb + (uint32_t)((s_) * STAGE_U + ST_VHI                            \
                                  + _row * VPITCH + _c7 * 4) * 4, _vs);             \
        }                                                                           \
    } while (0)

    ATTN_ISSUE(0, 0); CP_COMMIT();
    ATTN_ISSUE(1, 1); CP_COMMIT();

    // ---- Q fragments -> registers (pair-permuted global, LDG.64) ----
    uint32_t qh[4][4], ql[4][4];
    {
        const uint32_t* Qg  = (const uint32_t*)g_Qh + (base >> 1)
                              + (size_t)(qb * 128 + row0 + g) * 32;
        const uint32_t* Qgl = (const uint32_t*)g_Ql + (base >> 1)
                              + (size_t)(qb * 128 + row0 + g) * 32;
#pragma unroll
        for (int ks = 0; ks < 4; ks++) {
            uint2 a0 = *(const uint2*)(Qg + ks * 8 + 2 * tg);
            uint2 a1 = *(const uint2*)(Qg + 8 * 32 + ks * 8 + 2 * tg);
            qh[ks][0] = a0.x; qh[ks][1] = a1.x; qh[ks][2] = a0.y; qh[ks][3] = a1.y;
            uint2 b0 = *(const uint2*)(Qgl + ks * 8 + 2 * tg);
            uint2 b1 = *(const uint2*)(Qgl + 8 * 32 + ks * 8 + 2 * tg);
            ql[ks][0] = b0.x; ql[ks][1] = b1.x; ql[ks][2] = b0.y; ql[ks][3] = b1.y;
        }
    }

    float acc_o[8][4];
#pragma unroll
    for (int j = 0; j < 8; j++)
#pragma unroll
        for (int t = 0; t < 4; t++) acc_o[j][t] = 0.f;
    float m_run[2] = {-1.0e30f, -1.0e30f};
    float l_run[2] = {0.f, 0.f};

    const int ntiles = 2 * (qb + 1);
    for (int kb = 0; kb < ntiles; kb++) {
        CP_WAIT(1);
        __syncthreads();

        const int s = kb & 1;
        const uint32_t* Khi_s = smu + s * STAGE_U + ST_KHI;
        const uint32_t vhiB = sb + (uint32_t)(s * STAGE_U + ST_VHI) * 4;

        const bool active = (kb * 64 <= qb * 128 + row0 + 15);

        if (active) {
            // ---- S = Q K^T (2-term: qh*kh + ql*kh; K fp16-rounded) ----
            float s_acc[8][4];
#pragma unroll
            for (int j = 0; j < 8; j++)
#pragma unroll
                for (int t = 0; t < 4; t++) s_acc[j][t] = 0.f;

#pragma unroll
            for (int ks = 0; ks < 4; ks++) {
#pragma unroll
                for (int fn = 0; fn < 8; fn++) {
                    const int o = (fn * 8 + g) * KPITCH + ks * 8 + 2 * tg;
                    uint2 bh = *(const uint2*)(Khi_s + o);
                    mma_f16(s_acc[fn], qh[ks], bh.x, bh.y);
                    mma_f16(s_acc[fn], ql[ks], bh.x, bh.y);
                }
            }

            // ---- mask + online softmax (base-2) + pack P (hi only) ----
            uint32_t php[8][2];
            const bool diag = (kb >= 2 * qb);
#pragma unroll
            for (int h = 0; h < 2; h++) {
                if (diag) {
                    int row = qb * 128 + row0 + g + 8 * h;
#pragma unroll
                    for (int fn = 0; fn < 8; fn++) {
                        int col = kb * 64 + fn * 8 + 2 * tg;
                        if (col > row)     s_acc[fn][h * 2 + 0] = -1.0e30f;
                        if (col + 1 > row) s_acc[fn][h * 2 + 1] = -1.0e30f;
                    }
                }
                float mx = s_acc[0][h * 2];
#pragma unroll
                for (int fn = 0; fn < 8; fn++) {
                    mx = fmaxf(mx, s_acc[fn][h * 2 + 0]);
                    mx = fmaxf(mx, s_acc[fn][h * 2 + 1]);
                }
                mx = fmaxf(mx, __shfl_xor_sync(0xffffffffu, mx, 1));
                mx = fmaxf(mx, __shfl_xor_sync(0xffffffffu, mx, 2));
                float mn   = fmaxf(m_run[h], mx);
                float corr = exp2f(m_run[h] - mn);
                float rs = 0.f;
#pragma unroll
                for (int fn = 0; fn < 8; fn++) {
                    float p0 = exp2f(s_acc[fn][h * 2 + 0] - mn);
                    float p1 = exp2f(s_acc[fn][h * 2 + 1] - mn);
                    rs += p0 + p1;
                    php[fn][h] = h2u(__floats2half2_rn(p0, p1));
                }
                rs += __shfl_xor_sync(0xffffffffu, rs, 1);
                rs += __shfl_xor_sync(0xffffffffu, rs, 2);
                l_run[h] = l_run[h] * corr + rs;
                m_run[h] = mn;
#pragma unroll
                for (int fn = 0; fn < 8; fn++) {
                    acc_o[fn][h * 2 + 0] *= corr;
                    acc_o[fn][h * 2 + 1] *= corr;
                }
            }

            // ---- O += P V (P hi-only, V hi-only) ----
#pragma unroll
            for (int ks = 0; ks < 4; ks++) {
                uint32_t ahi[4] = { php[2 * ks][0], php[2 * ks][1],
                                    php[2 * ks + 1][0], php[2 * ks + 1][1] };
                const int vrow = ks * 16 + (lane & 15);
                const uint32_t abH = vhiB + (uint32_t)(vrow * VPITCH) * 4;
#pragma unroll
                for (int fn = 0; fn < 8; fn++) {
                    uint2 bh = ldsm_x2_trans(abH + fn * 16);
                    mma_f16(acc_o[fn], ahi, bh.x, bh.y);
                }
            }
        }

        __syncthreads();
        if (kb + 2 < ntiles) ATTN_ISSUE(kb + 2, s);
        CP_COMMIT();
    }
#undef ATTN_ISSUE

    // ---- normalize + write AO as fp16 hi, X-style pair-permutation ----
    // slot = ((fn>>1)<<3) + 2*tg + (fn&1)   (validated in R15)
    const int bb = bh >> 4, hh = bh & 15;
#pragma unroll
    for (int h = 0; h < 2; h++) {
        float invl = 1.0f / l_run[h];
        int row = qb * 128 + row0 + g + 8 * h;
        size_t rbase = ((size_t)bb * SLEN + row) * (DMODEL / 2) + hh * (DKH / 2);
        uint32_t* dsth = (uint32_t*)g_AOh + rbase;
#pragma unroll
        for (int fn = 0; fn < 8; fn++) {
            float o0 = acc_o[fn][h * 2 + 0] * invl;
            float o1 = acc_o[fn][h * 2 + 1] * invl;
            int slot = ((fn >> 1) << 3) + 2 * tg + (fn & 1);
            dsth[slot] = h2u(__floats2half2_rn(o0, o1));
        }
    }
}

// ---------------- launch -------------------------------------------------------
extern "C" void kernel_launch(void* const* d_in, const int* in_sizes, int n_in,
                              void* d_out, int out_size) {
    const float* q  = (const float*)d_in[0];
    const float* k  = (const float*)d_in[1];
    const float* v  = (const float*)d_in[2];
    // d_in[3] = mask (int32 tril) — causal, applied analytically
    const float* wq = (const float*)d_in[4];
    const float* bq = (const float*)d_in[5];
    const float* wk = (const float*)d_in[6];
    const float* bk = (const float*)d_in[7];
    const float* wv = (const float*)d_in[8];
    const float* bv = (const float*)d_in[9];
    const float* wo = (const float*)d_in[10];
    const float* bo = (const float*)d_in[11];
    float* out = (float*)d_out;

    cudaFuncSetAttribute(qkv_f16_kernel, cudaFuncAttributeMaxDynamicSharedMemorySize, GEMM_SMEM);
    cudaFuncSetAttribute(outproj_f16_kernel, cudaFuncAttributeMaxDynamicSharedMemorySize, GEMM_SMEM);
    cudaFuncSetAttribute(attn_hmma_kernel, cudaFuncAttributeMaxDynamicSharedMemorySize, ATTN_SMEM_BYTES);

    conv_all_kernel<<<7168, 256>>>(q, k, v, wq, wk, wv, wo);

    qkv_f16_kernel<<<dim3(DMODEL / 128, MTOT / 128, 3), 256, GEMM_SMEM>>>(bq, bk, bv);

    attn_hmma_kernel<<<dim3(SLEN / 128, NB * NHEAD), 256, ATTN_SMEM_BYTES>>>();

    outproj_f16_kernel<<<dim3(DMODEL / 128, MTOT / 128), 256, GEMM_SMEM>>>(bo, out);
}